// round 16
// baseline (speedup 1.0000x reference)
#include <cuda_runtime.h>
#include <cuda_fp16.h>
#include <cstdint>

#define Bn 32
#define Sn 512
#define En 256
#define Hn 8
#define HEn 2048
#define Mn 16384
#define BHn 256

typedef __half fp16;

// ---------------------------------------------------------------------------
// Scratch (device globals; allocation-free). Everything fp16; scores fp16
// in-place in g_Ph.
// ---------------------------------------------------------------------------
__device__ __align__(16) fp16 g_qh[(size_t)Mn * En];
__device__ __align__(16) fp16 g_kh[(size_t)Mn * En];
__device__ __align__(16) fp16 g_vh[(size_t)Mn * En];
__device__ __align__(16) fp16 g_Wqh[(size_t)Hn * En * En];
__device__ __align__(16) fp16 g_Wkh[(size_t)Hn * En * En];
__device__ __align__(16) fp16 g_Wvh[(size_t)Hn * En * En];
__device__ __align__(16) fp16 g_Woh[(size_t)En * HEn];
__device__ __align__(16) fp16 g_Qh[(size_t)BHn * Sn * En];
__device__ __align__(16) fp16 g_Kh[(size_t)BHn * Sn * En];
__device__ __align__(16) fp16 g_Vth[(size_t)BHn * En * Sn];
__device__ __align__(16) fp16 g_Ph[(size_t)BHn * Sn * Sn];   // S then P (in place)
__device__ __align__(16) fp16 g_Ch[(size_t)Mn * HEn];

// ---------------------------------------------------------------------------
// PTX helpers (arch-portable: ldmatrix + mma.sync + cp.async, sm_80+)
// ---------------------------------------------------------------------------
__device__ __forceinline__ uint32_t smem_u32(const void* p) {
    uint32_t a;
    asm("{ .reg .u64 t; cvta.to.shared.u64 t, %1; cvt.u32.u64 %0, t; }"
        : "=r"(a) : "l"(p));
    return a;
}
__device__ __forceinline__ void ldsm_x4(uint32_t* r, uint32_t a) {
    asm volatile("ldmatrix.sync.aligned.m8n8.x4.shared.b16 {%0,%1,%2,%3}, [%4];"
                 : "=r"(r[0]), "=r"(r[1]), "=r"(r[2]), "=r"(r[3]) : "r"(a));
}
__device__ __forceinline__ void ldsm_x2(uint32_t* r, uint32_t a) {
    asm volatile("ldmatrix.sync.aligned.m8n8.x2.shared.b16 {%0,%1}, [%2];"
                 : "=r"(r[0]), "=r"(r[1]) : "r"(a));
}
__device__ __forceinline__ void mma_f16(float* c, const uint32_t* a,
                                        const uint32_t* b) {
    asm volatile(
        "mma.sync.aligned.m16n8k16.row.col.f32.f16.f16.f32 "
        "{%0,%1,%2,%3}, {%4,%5,%6,%7}, {%8,%9}, {%0,%1,%2,%3};"
        : "+f"(c[0]), "+f"(c[1]), "+f"(c[2]), "+f"(c[3])
        : "r"(a[0]), "r"(a[1]), "r"(a[2]), "r"(a[3]), "r"(b[0]), "r"(b[1]));
}
__device__ __forceinline__ void cp16(uint32_t s, const void* g) {
    asm volatile("cp.async.cg.shared.global [%0], [%1], 16;" :: "r"(s), "l"(g));
}
#define CP_COMMIT() asm volatile("cp.async.commit_group;" ::: "memory")
#define CP_WAIT1()  asm volatile("cp.async.wait_group 1;"  ::: "memory")

__device__ __forceinline__ uint32_t pack_h(float x, float y) {
    __half2 h = __floats2half2_rn(x, y);
    return *reinterpret_cast<uint32_t*>(&h);
}

// Streamed-GEMM smem (attnv/outproj): 128x128B tiles, A|B per stage, 3 stages
#define TILEB  16384
#define STAGEB (2 * TILEB)
#define NSTAGE 3
#define SM_SMEM (NSTAGE * STAGEB)     // 98304/CTA; 2 CTAs/SM

// Big-GEMM smem: 256-row A|B tiles (32KB each) per stage, 3 stages
#define BG_TILEB  32768
#define BG_STAGEB 65536
#define BG_SMEM   196608              // 192KB/CTA; 1 CTA/SM, 16 warps

// ---------------------------------------------------------------------------
// Batched fp32 -> fp16 conversions (y selects tensor)
// ---------------------------------------------------------------------------
__global__ __launch_bounds__(256)
void cvt3_hi(const float* __restrict__ s0, const float* __restrict__ s1,
             const float* __restrict__ s2, fp16* __restrict__ d0,
             fp16* __restrict__ d1, fp16* __restrict__ d2, int n4)
{
    int i = blockIdx.x * blockDim.x + threadIdx.x;
    if (i >= n4) return;
    const float* s = (blockIdx.y == 0) ? s0 : (blockIdx.y == 1) ? s1 : s2;
    fp16* d = (blockIdx.y == 0) ? d0 : (blockIdx.y == 1) ? d1 : d2;
    float4 v = reinterpret_cast<const float4*>(s)[i];
    reinterpret_cast<uint2*>(d)[i] = make_uint2(pack_h(v.x, v.y), pack_h(v.z, v.w));
}
__global__ __launch_bounds__(256)
void cvt4_hi(const float* __restrict__ s0, const float* __restrict__ s1,
             const float* __restrict__ s2, const float* __restrict__ s3,
             fp16* __restrict__ d0, fp16* __restrict__ d1,
             fp16* __restrict__ d2, fp16* __restrict__ d3, int n4)
{
    int i = blockIdx.x * blockDim.x + threadIdx.x;
    if (i >= n4) return;
    const float* s = (blockIdx.y == 0) ? s0 : (blockIdx.y == 1) ? s1
                   : (blockIdx.y == 2) ? s2 : s3;
    fp16* d = (blockIdx.y == 0) ? d0 : (blockIdx.y == 1) ? d1
            : (blockIdx.y == 2) ? d2 : d3;
    float4 v = reinterpret_cast<const float4*>(s)[i];
    reinterpret_cast<uint2*>(d)[i] = make_uint2(pack_h(v.x, v.y), pack_h(v.z, v.w));
}

// ---------------------------------------------------------------------------
// Big fp16 HMMA NT GEMM: 256x256 CTA tile, 512 threads (16 warps, 4x4 grid,
// warp tile 64x64), K-chunk 64, cp.async 3-stage pipeline, 1 CTA/SM.
// MODE 0: merged QKV projection (N=256 = full head dim). grid (64, 24):
//         x = m-tile, y = z = pp*8+h. pp=0 Q, pp=1 K (pad), pp=2 Vt [BH,E,S].
// MODE 2: scores -> fp16 S (*1/16) into P. grid (3, 256): x indexes causal
//         256-tiles {(0,0),(1,0),(1,1)}, y = bh.
// ---------------------------------------------------------------------------
template <int MODE>
__global__ __launch_bounds__(512, 1)
void gemm_big(const fp16* __restrict__ A0, const fp16* __restrict__ A1,
              const fp16* __restrict__ A2, const fp16* __restrict__ B0,
              const fp16* __restrict__ B1, const fp16* __restrict__ B2,
              fp16* __restrict__ O0, fp16* __restrict__ O1,
              fp16* __restrict__ O2, const float* __restrict__ pad)
{
    extern __shared__ char smem[];
    const uint32_t sb = smem_u32(smem);
    const int tid = threadIdx.x, wid = tid >> 5, lane = tid & 31;

    int m0, n0, pp = 0, hh = 0, z = 0;
    const fp16 *Ah, *Bh;
    if constexpr (MODE == 0) {
        m0 = blockIdx.x * 256; n0 = 0;
        z = blockIdx.y; pp = z >> 3; hh = z & 7;
        const fp16* Ab = (pp == 0) ? A0 : (pp == 1) ? A1 : A2;
        const fp16* Bb = (pp == 0) ? B0 : (pp == 1) ? B1 : B2;
        Ah = Ab + (size_t)m0 * En;
        Bh = Bb + (size_t)hh * En * En;
    } else {
        const int mt_tab[3] = {0, 1, 1};
        const int nt_tab[3] = {0, 0, 1};
        m0 = mt_tab[blockIdx.x] * 256;
        n0 = nt_tab[blockIdx.x] * 256;
        z = blockIdx.y;
        Ah = A0 + (size_t)z * Sn * En + (size_t)m0 * En;
        Bh = B0 + (size_t)z * Sn * En + (size_t)n0 * En;
    }
    const int nc = En / 64;   // 4

    auto issue = [&](int cc) {
        const uint32_t st = sb + (uint32_t)(cc % NSTAGE) * BG_STAGEB;
        #pragma unroll
        for (int i = 0; i < 4; i++) {
            const int idx = i * 512 + tid;          // 0..2047
            const int row = idx >> 3, ch = idx & 7;
            const uint32_t so = (uint32_t)((row << 7) + (((ch ^ (row & 7))) << 4));
            cp16(st + so, Ah + (size_t)row * En + (size_t)cc * 64 + ch * 8);
            cp16(st + BG_TILEB + so, Bh + (size_t)row * En + (size_t)cc * 64 + ch * 8);
        }
    };

    issue(0); CP_COMMIT();
    issue(1); CP_COMMIT();

    const int wm = wid & 3, wn = wid >> 2;          // 4x4 grid, tile 64x64
    const int arow = wm * 64 + (lane & 15), a7 = arow & 7, ac = lane >> 4;
    const int brow = wn * 64 + (lane & 7),  b7 = lane & 7,  bc = (lane >> 3) & 1;

    float c[4][8][4] = {};

    for (int cc = 0; cc < nc; ++cc) {
        CP_WAIT1();
        __syncthreads();
        if (cc + 2 < nc) issue(cc + 2);
        CP_COMMIT();

        const uint32_t st = sb + (uint32_t)(cc % NSTAGE) * BG_STAGEB;
        #pragma unroll
        for (int kb = 0; kb < 4; kb++) {
            const uint32_t asw = (uint32_t)(((kb * 2 + ac) ^ a7) << 4);
            const uint32_t bsw = (uint32_t)(((kb * 2 + bc) ^ b7) << 4);
            uint32_t a[4][4], b[8][2];
            #pragma unroll
            for (int ma = 0; ma < 4; ma++)
                ldsm_x4(a[ma], st + (uint32_t)((arow + ma * 16) << 7) + asw);
            #pragma unroll
            for (int na = 0; na < 8; na++)
                ldsm_x2(b[na], st + BG_TILEB + (uint32_t)((brow + na * 8) << 7) + bsw);
            #pragma unroll
            for (int ma = 0; ma < 4; ma++)
                #pragma unroll
                for (int na = 0; na < 8; na++)
                    mma_f16(c[ma][na], a[ma], b[na]);
        }
    }

    const int g = lane >> 2, tig = lane & 3;

    if (MODE == 0 && pp == 2) {
        // V projection: stage fp16 in smem (stride 260), write Vt [BH,E,S]
        __syncthreads();
        fp16* ts = reinterpret_cast<fp16*>(smem);
        #pragma unroll
        for (int ma = 0; ma < 4; ma++) {
            const int rl = wm * 64 + ma * 16 + g;
            #pragma unroll
            for (int na = 0; na < 8; na++) {
                const int cl = wn * 64 + na * 8 + 2 * tig;
                *reinterpret_cast<uint32_t*>(&ts[rl * 260 + cl]) =
                    pack_h(c[ma][na][0], c[ma][na][1]);
                *reinterpret_cast<uint32_t*>(&ts[(rl + 8) * 260 + cl]) =
                    pack_h(c[ma][na][2], c[ma][na][3]);
            }
        }
        __syncthreads();
        const int bb = m0 >> 9, sbase = m0 & 511;
        for (int i = tid; i < 256 * 128; i += 512) {
            const int d = i >> 7, s2 = (i & 127) * 2;
            __half2 h2 = __halves2half2(ts[s2 * 260 + d], ts[(s2 + 1) * 260 + d]);
            size_t o = (((size_t)(bb * Hn + hh)) * En + d) * Sn + sbase + s2;
            *reinterpret_cast<uint32_t*>(O2 + o) = *reinterpret_cast<uint32_t*>(&h2);
        }
        return;
    }

    #pragma unroll
    for (int ma = 0; ma < 4; ma++) {
        const int r0 = m0 + wm * 64 + ma * 16 + g;
        const int r1 = r0 + 8;
        float s0 = 1.0f, s1 = 1.0f;
        if constexpr (MODE == 0) {
            if (pp == 1) { s0 = pad[r0]; s1 = pad[r1]; }
        }
        #pragma unroll
        for (int na = 0; na < 8; na++) {
            const int cb = n0 + wn * 64 + na * 8 + 2 * tig;
            const float v0 = c[ma][na][0], v1 = c[ma][na][1];
            const float v2 = c[ma][na][2], v3 = c[ma][na][3];
            if constexpr (MODE == 0) {
                fp16* Oh = (pp == 0) ? O0 : O1;
                size_t o0 = (((size_t)((r0 >> 9) * Hn + hh)) * Sn + (r0 & 511)) * En + cb;
                size_t o1 = (((size_t)((r1 >> 9) * Hn + hh)) * Sn + (r1 & 511)) * En + cb;
                *reinterpret_cast<uint32_t*>(Oh + o0) = pack_h(v0 * s0, v1 * s0);
                *reinterpret_cast<uint32_t*>(Oh + o1) = pack_h(v2 * s1, v3 * s1);
            } else {
                size_t o0 = (size_t)z * Sn * Sn + (size_t)r0 * Sn + cb;
                size_t o1 = (size_t)z * Sn * Sn + (size_t)r1 * Sn + cb;
                *reinterpret_cast<uint32_t*>(O0 + o0) = pack_h(v0 * 0.0625f, v1 * 0.0625f);
                *reinterpret_cast<uint32_t*>(O0 + o1) = pack_h(v2 * 0.0625f, v3 * 0.0625f);
            }
        }
    }
}

// ---------------------------------------------------------------------------
// Streamed fp16 HMMA NT GEMM (attnv + outproj), proven R13 geometry.
// MODE 3: attnv -> fp16 concat [B,S,H*E], K truncated at causal bound
// MODE 4: outproj -> fp32 d_out + bias
// ---------------------------------------------------------------------------
template <int MODE>
__global__ __launch_bounds__(256, 2)
void gemm_hf(const fp16* __restrict__ A0, const fp16* __restrict__ B0,
             void* __restrict__ O0, const float* __restrict__ bias)
{
    extern __shared__ char smem[];
    const uint32_t sb = smem_u32(smem);
    const int tid = threadIdx.x, wid = tid >> 5, lane = tid & 31;
    const int z = blockIdx.z;
    const int m0 = blockIdx.y * 128, n0 = blockIdx.x * 128;

    const fp16 *Ah, *Bh;
    int lda, ldb, nc;
    if constexpr (MODE == 3) {
        Ah = A0 + (size_t)z * Sn * Sn + (size_t)m0 * Sn;
        Bh = B0 + (size_t)z * En * Sn + (size_t)n0 * Sn;
        lda = Sn; ldb = Sn; nc = (m0 + 128) / 64;
    } else {
        Ah = A0 + (size_t)m0 * HEn;
        Bh = B0 + (size_t)n0 * HEn;
        lda = HEn; ldb = HEn; nc = HEn / 64;
    }

    auto issue = [&](int cc) {
        const uint32_t st = sb + (uint32_t)(cc % NSTAGE) * STAGEB;
        #pragma unroll
        for (int i = 0; i < 4; i++) {
            const int idx = i * 256 + tid;
            const int row = idx >> 3, ch = idx & 7;
            const uint32_t so = (uint32_t)((row << 7) + (((ch ^ (row & 7))) << 4));
            cp16(st + so, Ah + (size_t)row * lda + (size_t)cc * 64 + ch * 8);
            cp16(st + TILEB + so, Bh + (size_t)row * ldb + (size_t)cc * 64 + ch * 8);
        }
    };

    issue(0); CP_COMMIT();
    issue(1); CP_COMMIT();

    const int wm = wid & 3, wn = wid >> 2;
    const int arow = wm * 32 + (lane & 15), a7 = arow & 7, ac = lane >> 4;
    const int brow = wn * 64 + (lane & 7),  b7 = lane & 7,  bc = (lane >> 3) & 1;

    float c[2][8][4] = {};

    for (int cc = 0; cc < nc; ++cc) {
        CP_WAIT1();
        __syncthreads();
        if (cc + 2 < nc) issue(cc + 2);
        CP_COMMIT();

        const uint32_t st = sb + (uint32_t)(cc % NSTAGE) * STAGEB;
        #pragma unroll
        for (int kb = 0; kb < 4; kb++) {
            const uint32_t asw = (uint32_t)(((kb * 2 + ac) ^ a7) << 4);
            const uint32_t bsw = (uint32_t)(((kb * 2 + bc) ^ b7) << 4);
            uint32_t ah[2][4], bh[8][2];
            #pragma unroll
            for (int ma = 0; ma < 2; ma++)
                ldsm_x4(ah[ma], st + (uint32_t)((arow + ma * 16) << 7) + asw);
            #pragma unroll
            for (int na = 0; na < 8; na++)
                ldsm_x2(bh[na], st + TILEB + (uint32_t)((brow + na * 8) << 7) + bsw);
            #pragma unroll
            for (int ma = 0; ma < 2; ma++)
                #pragma unroll
                for (int na = 0; na < 8; na++)
                    mma_f16(c[ma][na], ah[ma], bh[na]);
        }
    }

    const int g = lane >> 2, tig = lane & 3;
    #pragma unroll
    for (int ma = 0; ma < 2; ma++) {
        const int r0 = m0 + wm * 32 + ma * 16 + g;
        const int r1 = r0 + 8;
        #pragma unroll
        for (int na = 0; na < 8; na++) {
            const int cb = n0 + wn * 64 + na * 8 + 2 * tig;
            const float v0 = c[ma][na][0], v1 = c[ma][na][1];
            const float v2 = c[ma][na][2], v3 = c[ma][na][3];
            if constexpr (MODE == 3) {
                fp16* Oh = (fp16*)O0;
                size_t o0 = ((size_t)((z >> 3) * Sn + r0)) * HEn + (z & 7) * En + cb;
                size_t o1 = ((size_t)((z >> 3) * Sn + r1)) * HEn + (z & 7) * En + cb;
                *reinterpret_cast<uint32_t*>(Oh + o0) = pack_h(v0, v1);
                *reinterpret_cast<uint32_t*>(Oh + o1) = pack_h(v2, v3);
            } else {
                float* O = (float*)O0;
                const float bx = bias[cb], by = bias[cb + 1];
                float* p0 = O + (size_t)r0 * En + cb;
                float* p1 = O + (size_t)r1 * En + cb;
                *reinterpret_cast<float2*>(p0) = make_float2(v0 + bx, v1 + by);
                *reinterpret_cast<float2*>(p1) = make_float2(v2 + bx, v3 + by);
            }
        }
    }
}

// ---------------------------------------------------------------------------
// Warp-per-row causal softmax, in place on fp16 S/P. 16 rows / 512-thr block.
// ---------------------------------------------------------------------------
__global__ __launch_bounds__(512)
void softmax_inplace(fp16* __restrict__ P)
{
    const int wid = threadIdx.x >> 5, lane = threadIdx.x & 31;
    const size_t row = (size_t)blockIdx.x * 16 + wid;
    const int q = (int)(row & (Sn - 1));
    uint2* p = reinterpret_cast<uint2*>(P + row * Sn);
    const int ng = (q >> 7) + 1;

    float f[4][4];
    float m = -1e30f;
    #pragma unroll
    for (int gI = 0; gI < 4; gI++) {
        if (gI < ng) {
            uint2 x = p[gI * 32 + lane];
            const __half2* hp = reinterpret_cast<const __half2*>(&x);
            float2 a = __half22float2(hp[0]);
            float2 b = __half22float2(hp[1]);
            const int k = (gI * 32 + lane) * 4;
            f[gI][0] = (k + 0 <= q) ? a.x : -1e30f;
            f[gI][1] = (k + 1 <= q) ? a.y : -1e30f;
            f[gI][2] = (k + 2 <= q) ? b.x : -1e30f;
            f[gI][3] = (k + 3 <= q) ? b.y : -1e30f;
            m = fmaxf(m, fmaxf(fmaxf(f[gI][0], f[gI][1]),
                               fmaxf(f[gI][2], f[gI][3])));
        }
    }
    #pragma unroll
    for (int o = 16; o; o >>= 1) m = fmaxf(m, __shfl_xor_sync(0xffffffffu, m, o));

    float s = 0.0f;
    #pragma unroll
    for (int gI = 0; gI < 4; gI++) {
        if (gI < ng) {
            #pragma unroll
            for (int i = 0; i < 4; i++) { f[gI][i] = __expf(f[gI][i] - m); s += f[gI][i]; }
        }
    }
    #pragma unroll
    for (int o = 16; o; o >>= 1) s += __shfl_xor_sync(0xffffffffu, s, o);
    const float inv = 1.0f / s;

    #pragma unroll
    for (int gI = 0; gI < 4; gI++) {
        if (gI < ng) {
            uint2 o;
            o.x = pack_h(f[gI][0] * inv, f[gI][1] * inv);
            o.y = pack_h(f[gI][2] * inv, f[gI][3] * inv);
            p[gI * 32 + lane] = o;
        }
    }
}

// ---------------------------------------------------------------------------
// Launch (my index 3 = scores gemm_big<2> — the launch ncu profiles)
// ---------------------------------------------------------------------------
extern "C" void kernel_launch(void* const* d_in, const int* in_sizes, int n_in,
                              void* d_out, int out_size)
{
    const float* q   = (const float*)d_in[0];
    const float* k   = (const float*)d_in[1];
    const float* v   = (const float*)d_in[2];
    const float* pad = (const float*)d_in[3];
    // d_in[4] = attn_mask (causal applied analytically)
    const float* Wq  = (const float*)d_in[5];
    const float* Wk  = (const float*)d_in[6];
    const float* Wv  = (const float*)d_in[7];
    const float* Wo  = (const float*)d_in[8];
    const float* bo  = (const float*)d_in[9];
    float* out = (float*)d_out;

    fp16 *qh, *kh, *vh, *Wqh, *Wkh, *Wvh, *Woh;
    fp16 *Qh, *Kh, *Vth, *Ph, *Ch;
    cudaGetSymbolAddress((void**)&qh,  g_qh);
    cudaGetSymbolAddress((void**)&kh,  g_kh);
    cudaGetSymbolAddress((void**)&vh,  g_vh);
    cudaGetSymbolAddress((void**)&Wqh, g_Wqh);
    cudaGetSymbolAddress((void**)&Wkh, g_Wkh);
    cudaGetSymbolAddress((void**)&Wvh, g_Wvh);
    cudaGetSymbolAddress((void**)&Woh, g_Woh);
    cudaGetSymbolAddress((void**)&Qh,  g_Qh);
    cudaGetSymbolAddress((void**)&Kh,  g_Kh);
    cudaGetSymbolAddress((void**)&Vth, g_Vth);
    cudaGetSymbolAddress((void**)&Ph,  g_Ph);
    cudaGetSymbolAddress((void**)&Ch,  g_Ch);

    cudaFuncSetAttribute((const void*)gemm_big<0>, cudaFuncAttributeMaxDynamicSharedMemorySize, BG_SMEM);
    cudaFuncSetAttribute((const void*)gemm_big<2>, cudaFuncAttributeMaxDynamicSharedMemorySize, BG_SMEM);
    cudaFuncSetAttribute((const void*)gemm_hf<3>,  cudaFuncAttributeMaxDynamicSharedMemorySize, SM_SMEM);
    cudaFuncSetAttribute((const void*)gemm_hf<4>,  cudaFuncAttributeMaxDynamicSharedMemorySize, SM_SMEM);

    const int n4x = Mn * En / 4;          // 1048576
    const int n4w = Hn * En * En / 4;     // 131072

    // index 0-1: batched conversions
    cvt3_hi<<<dim3(n4x / 256, 3), 256>>>(q, k, v, qh, kh, vh, n4x);
    cvt4_hi<<<dim3(n4w / 256, 4), 256>>>(Wq, Wk, Wv, Wo, Wqh, Wkh, Wvh, Woh, n4w);

    // index 2: merged QKV projections, 256x256 tiles, grid (64, 24)
    gemm_big<0><<<dim3(64, 24), 512, BG_SMEM>>>(
        qh, kh, vh, Wqh, Wkh, Wvh, Qh, Kh, Vth, pad);

    // index 3 (profiled): scores 256-tiles {(0,0),(1,0),(1,1)} x 256 bh
    gemm_big<2><<<dim3(3, 256), 512, BG_SMEM>>>(
        Qh, nullptr, nullptr, Kh, nullptr, nullptr, Ph, nullptr, nullptr,
        nullptr);

    // in-place warp-per-row softmax
    softmax_inplace<<<BHn * Sn / 16, 512>>>(Ph);

    // attn @ V: (2,4,256), K truncated at causal boundary
    gemm_hf<3><<<dim3(2, 4, 256), 256, SM_SMEM>>>(Ph, Vth, Ch, nullptr);

    // out projection: (2,128)
    gemm_hf<4><<<dim3(2, 128, 1), 256, SM_SMEM>>>(Ch, Woh, out, bo);
}

// round 17
// speedup vs baseline: 2.0891x; 2.0891x over previous
#include <cuda_runtime.h>
#include <cuda_fp16.h>
#include <cstdint>

#define Bn 32
#define Sn 512
#define En 256
#define Hn 8
#define HEn 2048
#define Mn 16384
#define BHn 256

typedef __half fp16;

// ---------------------------------------------------------------------------
// Scratch (device globals; allocation-free). Everything fp16; scores are
// written fp16 directly into g_Ph and softmaxed in place.
// ---------------------------------------------------------------------------
__device__ __align__(16) fp16 g_qh[(size_t)Mn * En];
__device__ __align__(16) fp16 g_kh[(size_t)Mn * En];
__device__ __align__(16) fp16 g_vh[(size_t)Mn * En];
__device__ __align__(16) fp16 g_Wqh[(size_t)Hn * En * En];
__device__ __align__(16) fp16 g_Wkh[(size_t)Hn * En * En];
__device__ __align__(16) fp16 g_Wvh[(size_t)Hn * En * En];
__device__ __align__(16) fp16 g_Woh[(size_t)En * HEn];
__device__ __align__(16) fp16 g_Qh[(size_t)BHn * Sn * En];
__device__ __align__(16) fp16 g_Kh[(size_t)BHn * Sn * En];
__device__ __align__(16) fp16 g_Vth[(size_t)BHn * En * Sn];
__device__ __align__(16) fp16 g_Ph[(size_t)BHn * Sn * Sn];   // S then P (in place)
__device__ __align__(16) fp16 g_Ch[(size_t)Mn * HEn];

// ---------------------------------------------------------------------------
// PTX helpers (arch-portable: ldmatrix + mma.sync + cp.async, sm_80+)
// ---------------------------------------------------------------------------
__device__ __forceinline__ uint32_t smem_u32(const void* p) {
    uint32_t a;
    asm("{ .reg .u64 t; cvta.to.shared.u64 t, %1; cvt.u32.u64 %0, t; }"
        : "=r"(a) : "l"(p));
    return a;
}
__device__ __forceinline__ void ldsm_x4(uint32_t* r, uint32_t a) {
    asm volatile("ldmatrix.sync.aligned.m8n8.x4.shared.b16 {%0,%1,%2,%3}, [%4];"
                 : "=r"(r[0]), "=r"(r[1]), "=r"(r[2]), "=r"(r[3]) : "r"(a));
}
__device__ __forceinline__ void mma_f16(float* c, const uint32_t* a,
                                        const uint32_t* b) {
    asm volatile(
        "mma.sync.aligned.m16n8k16.row.col.f32.f16.f16.f32 "
        "{%0,%1,%2,%3}, {%4,%5,%6,%7}, {%8,%9}, {%0,%1,%2,%3};"
        : "+f"(c[0]), "+f"(c[1]), "+f"(c[2]), "+f"(c[3])
        : "r"(a[0]), "r"(a[1]), "r"(a[2]), "r"(a[3]), "r"(b[0]), "r"(b[1]));
}
__device__ __forceinline__ void cp16(uint32_t s, const void* g) {
    asm volatile("cp.async.cg.shared.global [%0], [%1], 16;" :: "r"(s), "l"(g));
}
#define CP_COMMIT() asm volatile("cp.async.commit_group;" ::: "memory")
#define CP_WAIT1()  asm volatile("cp.async.wait_group 1;"  ::: "memory")

__device__ __forceinline__ uint32_t pack_h(float x, float y) {
    __half2 h = __floats2half2_rn(x, y);
    return *reinterpret_cast<uint32_t*>(&h);
}

// smem tile geometry: 128 rows x 128B (64 fp16 K-chunk), XOR-16B swizzled,
// A|B per stage, 3 stages.
#define TILEB  16384
#define STAGEB (2 * TILEB)
#define NSTAGE 3
#define SM_SMEM (NSTAGE * STAGEB)   // 98304/CTA; 2 CTAs = 196608

// ---------------------------------------------------------------------------
// Batched fp32 -> fp16 conversions (y selects tensor)
// ---------------------------------------------------------------------------
__global__ __launch_bounds__(256)
void cvt3_hi(const float* __restrict__ s0, const float* __restrict__ s1,
             const float* __restrict__ s2, fp16* __restrict__ d0,
             fp16* __restrict__ d1, fp16* __restrict__ d2, int n4)
{
    int i = blockIdx.x * blockDim.x + threadIdx.x;
    if (i >= n4) return;
    const float* s = (blockIdx.y == 0) ? s0 : (blockIdx.y == 1) ? s1 : s2;
    fp16* d = (blockIdx.y == 0) ? d0 : (blockIdx.y == 1) ? d1 : d2;
    float4 v = reinterpret_cast<const float4*>(s)[i];
    reinterpret_cast<uint2*>(d)[i] = make_uint2(pack_h(v.x, v.y), pack_h(v.z, v.w));
}
__global__ __launch_bounds__(256)
void cvt4_hi(const float* __restrict__ s0, const float* __restrict__ s1,
             const float* __restrict__ s2, const float* __restrict__ s3,
             fp16* __restrict__ d0, fp16* __restrict__ d1,
             fp16* __restrict__ d2, fp16* __restrict__ d3, int n4)
{
    int i = blockIdx.x * blockDim.x + threadIdx.x;
    if (i >= n4) return;
    const float* s = (blockIdx.y == 0) ? s0 : (blockIdx.y == 1) ? s1
                   : (blockIdx.y == 2) ? s2 : s3;
    fp16* d = (blockIdx.y == 0) ? d0 : (blockIdx.y == 1) ? d1
            : (blockIdx.y == 2) ? d2 : d3;
    float4 v = reinterpret_cast<const float4*>(s)[i];
    reinterpret_cast<uint2*>(d)[i] = make_uint2(pack_h(v.x, v.y), pack_h(v.z, v.w));
}

// ---------------------------------------------------------------------------
// Single-pass fp16 HMMA NT GEMM. 128x128 CTA tile, 8 warps (4x2 grid, warp
// tile 32x64), K-chunk 64, cp.async 3-stage pipeline, 2 CTAs/SM.
// B fragments loaded via ldmatrix.x4 (two n8k16 frags per instruction).
// MODE 0: merged QKV projection. z=pp*8+h; pp=0: Q; pp=1: K (pad row scale);
//         pp=2: V transposed -> [BH,E,S].
// MODE 2: scores -> fp16 S (*1/16) into P buffer; 10 lower-triangular tiles
// MODE 3: attnv -> fp16 concat [B,S,H*E], K truncated at causal bound
// MODE 4: outproj -> fp32 d_out + bias
// ---------------------------------------------------------------------------
template <int MODE>
__global__ __launch_bounds__(256, 2)
void gemm_hf(const fp16* __restrict__ A0, const fp16* __restrict__ A1,
             const fp16* __restrict__ A2, const fp16* __restrict__ B0,
             const fp16* __restrict__ B1, const fp16* __restrict__ B2,
             void* __restrict__ O0, void* __restrict__ O1,
             void* __restrict__ O2,
             const float* __restrict__ pad, const float* __restrict__ bias)
{
    extern __shared__ char smem[];
    const uint32_t sb = smem_u32(smem);
    const int tid = threadIdx.x, wid = tid >> 5, lane = tid & 31;
    const int z = blockIdx.z;

    int m0, n0;
    if constexpr (MODE == 2) {
        const int mt_tab[10] = {0,1,1,2,2,2,3,3,3,3};
        const int nt_tab[10] = {0,0,1,0,1,2,0,1,2,3};
        m0 = mt_tab[blockIdx.x] * 128;
        n0 = nt_tab[blockIdx.x] * 128;
    } else {
        m0 = blockIdx.y * 128;
        n0 = blockIdx.x * 128;
    }

    int pp = 0, hh = 0;
    const fp16 *Ah, *Bh;
    int lda, ldb, nc;
    if constexpr (MODE == 0) {
        pp = z >> 3; hh = z & 7;
        const fp16* Ab = (pp == 0) ? A0 : (pp == 1) ? A1 : A2;
        const fp16* Bb = (pp == 0) ? B0 : (pp == 1) ? B1 : B2;
        Ah = Ab + (size_t)m0 * En;
        Bh = Bb + (size_t)hh * En * En + (size_t)n0 * En;
        lda = En; ldb = En; nc = En / 64;
    } else if constexpr (MODE == 2) {
        Ah = A0 + (size_t)z * Sn * En + (size_t)m0 * En;
        Bh = B0 + (size_t)z * Sn * En + (size_t)n0 * En;
        lda = En; ldb = En; nc = En / 64;
    } else if constexpr (MODE == 3) {
        Ah = A0 + (size_t)z * Sn * Sn + (size_t)m0 * Sn;
        Bh = B0 + (size_t)z * En * Sn + (size_t)n0 * Sn;
        lda = Sn; ldb = Sn; nc = (m0 + 128) / 64;   // causal truncation
    } else {
        Ah = A0 + (size_t)m0 * HEn;
        Bh = B0 + (size_t)n0 * HEn;
        lda = HEn; ldb = HEn; nc = HEn / 64;
    }

    auto issue = [&](int cc) {
        const uint32_t st = sb + (uint32_t)(cc % NSTAGE) * STAGEB;
        #pragma unroll
        for (int i = 0; i < 4; i++) {
            const int idx = i * 256 + tid;
            const int row = idx >> 3, ch = idx & 7;
            const uint32_t so = (uint32_t)((row << 7) + (((ch ^ (row & 7))) << 4));
            const size_t ga = (size_t)row * lda + (size_t)cc * 64 + ch * 8;
            const size_t gb = (size_t)row * ldb + (size_t)cc * 64 + ch * 8;
            cp16(st + so, Ah + ga);
            cp16(st + TILEB + so, Bh + gb);
        }
    };

    issue(0); CP_COMMIT();
    issue(1); CP_COMMIT();

    const int wm = wid & 3, wn = wid >> 2;
    const int arow = wm * 32 + (lane & 15);
    const int a7   = arow & 7;
    const int ac   = lane >> 4;
    // B via ldmatrix.x4: lanes 0-7 -> na rows (k-half 0), 8-15 -> na rows
    // (k-half 1), 16-23 -> na+1 rows (k-half 0), 24-31 -> na+1 (k-half 1).
    const int browx = wn * 64 + (lane & 7) + ((lane >> 4) & 1) * 8;
    const int b7    = lane & 7;             // low 3 bits of browx
    const int bc    = (lane >> 3) & 1;

    float c[2][8][4] = {};

    for (int cc = 0; cc < nc; ++cc) {
        CP_WAIT1();
        __syncthreads();
        if (cc + 2 < nc) issue(cc + 2);
        CP_COMMIT();

        const uint32_t st = sb + (uint32_t)(cc % NSTAGE) * STAGEB;
        #pragma unroll
        for (int kb = 0; kb < 4; kb++) {
            const uint32_t asw = (uint32_t)(((kb * 2 + ac) ^ a7) << 4);
            const uint32_t bsw = (uint32_t)(((kb * 2 + bc) ^ b7) << 4);
            uint32_t ah[2][4], b4[4][4];
            #pragma unroll
            for (int ma = 0; ma < 2; ma++)
                ldsm_x4(ah[ma], st + (uint32_t)((arow + ma * 16) << 7) + asw);
            #pragma unroll
            for (int n2 = 0; n2 < 4; n2++)
                ldsm_x4(b4[n2], st + TILEB
                        + (uint32_t)((browx + n2 * 16) << 7) + bsw);
            #pragma unroll
            for (int ma = 0; ma < 2; ma++)
                #pragma unroll
                for (int n2 = 0; n2 < 4; n2++) {
                    mma_f16(c[ma][n2 * 2],     ah[ma], &b4[n2][0]);
                    mma_f16(c[ma][n2 * 2 + 1], ah[ma], &b4[n2][2]);
                }
        }
    }

    const int g = lane >> 2, tig = lane & 3;

    if (MODE == 0 && pp == 2) {
        // V projection: stage fp32 in smem, write transposed fp16 [BH,E,S]
        float* ts = reinterpret_cast<float*>(smem);
        __syncthreads();
        #pragma unroll
        for (int ma = 0; ma < 2; ma++) {
            const int rl = wm * 32 + ma * 16 + g;
            #pragma unroll
            for (int na = 0; na < 8; na++) {
                const int cl = wn * 64 + na * 8 + 2 * tig;
                ts[rl * 132 + cl]           = c[ma][na][0];
                ts[rl * 132 + cl + 1]       = c[ma][na][1];
                ts[(rl + 8) * 132 + cl]     = c[ma][na][2];
                ts[(rl + 8) * 132 + cl + 1] = c[ma][na][3];
            }
        }
        __syncthreads();
        fp16* Oh = (fp16*)O2;
        const int bb = m0 >> 9, sbase = m0 & 511;
        for (int i = tid; i < 128 * 64; i += 256) {
            const int d = i >> 6, s2 = (i & 63) * 2;
            float v0 = ts[s2 * 132 + d], v1 = ts[(s2 + 1) * 132 + d];
            size_t o = (((size_t)(bb * Hn + hh)) * En + n0 + d) * Sn + sbase + s2;
            *reinterpret_cast<uint32_t*>(Oh + o) = pack_h(v0, v1);
        }
        return;
    }

    #pragma unroll
    for (int ma = 0; ma < 2; ma++) {
        const int r0 = m0 + wm * 32 + ma * 16 + g;
        const int r1 = r0 + 8;
        float s0 = 1.0f, s1 = 1.0f;
        if constexpr (MODE == 0) {
            if (pp == 1) { s0 = pad[r0]; s1 = pad[r1]; }
        }
        #pragma unroll
        for (int na = 0; na < 8; na++) {
            const int cb = n0 + wn * 64 + na * 8 + 2 * tig;
            const float v0 = c[ma][na][0], v1 = c[ma][na][1];
            const float v2 = c[ma][na][2], v3 = c[ma][na][3];
            if constexpr (MODE == 0) {
                fp16* Oh = (fp16*)((pp == 0) ? O0 : O1);
                size_t o0 = (((size_t)((r0 >> 9) * Hn + hh)) * Sn + (r0 & 511)) * En + cb;
                size_t o1 = (((size_t)((r1 >> 9) * Hn + hh)) * Sn + (r1 & 511)) * En + cb;
                *reinterpret_cast<uint32_t*>(Oh + o0) = pack_h(v0 * s0, v1 * s0);
                *reinterpret_cast<uint32_t*>(Oh + o1) = pack_h(v2 * s1, v3 * s1);
            } else if constexpr (MODE == 2) {
                fp16* Oh = (fp16*)O0;
                size_t o0 = (size_t)z * Sn * Sn + (size_t)r0 * Sn + cb;
                size_t o1 = (size_t)z * Sn * Sn + (size_t)r1 * Sn + cb;
                *reinterpret_cast<uint32_t*>(Oh + o0) = pack_h(v0 * 0.0625f, v1 * 0.0625f);
                *reinterpret_cast<uint32_t*>(Oh + o1) = pack_h(v2 * 0.0625f, v3 * 0.0625f);
            } else if constexpr (MODE == 3) {
                fp16* Oh = (fp16*)O0;
                size_t o0 = ((size_t)((z >> 3) * Sn + r0)) * HEn + (z & 7) * En + cb;
                size_t o1 = ((size_t)((z >> 3) * Sn + r1)) * HEn + (z & 7) * En + cb;
                *reinterpret_cast<uint32_t*>(Oh + o0) = pack_h(v0, v1);
                *reinterpret_cast<uint32_t*>(Oh + o1) = pack_h(v2, v3);
            } else {
                float* O = (float*)O0;
                const float bx = bias[cb], by = bias[cb + 1];
                float* p0 = O + (size_t)r0 * En + cb;
                float* p1 = O + (size_t)r1 * En + cb;
                *reinterpret_cast<float2*>(p0) = make_float2(v0 + bx, v1 + by);
                *reinterpret_cast<float2*>(p1) = make_float2(v2 + bx, v3 + by);
            }
        }
    }
}

// ---------------------------------------------------------------------------
// Warp-per-row causal softmax, IN PLACE on fp16 S/P buffer.
// 16 rows per 512-thread block; shuffle-only reductions; uint2 (4 fp16)
// per lane per 128-col group; touches only k < tend = ((q>>7)+1)*128.
// ---------------------------------------------------------------------------
__global__ __launch_bounds__(512)
void softmax_inplace(fp16* __restrict__ P)
{
    const int wid = threadIdx.x >> 5, lane = threadIdx.x & 31;
    const size_t row = (size_t)blockIdx.x * 16 + wid;
    const int q = (int)(row & (Sn - 1));
    uint2* p = reinterpret_cast<uint2*>(P + row * Sn);
    const int ng = (q >> 7) + 1;           // 1..4 groups of 128 cols

    float f[4][4];
    float m = -1e30f;
    #pragma unroll
    for (int gI = 0; gI < 4; gI++) {
        if (gI < ng) {
            uint2 x = p[gI * 32 + lane];
            const __half2* hp = reinterpret_cast<const __half2*>(&x);
            float2 a = __half22float2(hp[0]);
            float2 b = __half22float2(hp[1]);
            const int k = (gI * 32 + lane) * 4;
            f[gI][0] = (k + 0 <= q) ? a.x : -1e30f;
            f[gI][1] = (k + 1 <= q) ? a.y : -1e30f;
            f[gI][2] = (k + 2 <= q) ? b.x : -1e30f;
            f[gI][3] = (k + 3 <= q) ? b.y : -1e30f;
            m = fmaxf(m, fmaxf(fmaxf(f[gI][0], f[gI][1]),
                               fmaxf(f[gI][2], f[gI][3])));
        }
    }
    #pragma unroll
    for (int o = 16; o; o >>= 1) m = fmaxf(m, __shfl_xor_sync(0xffffffffu, m, o));

    float s = 0.0f;
    #pragma unroll
    for (int gI = 0; gI < 4; gI++) {
        if (gI < ng) {
            #pragma unroll
            for (int i = 0; i < 4; i++) {
                f[gI][i] = __expf(f[gI][i] - m);
                s += f[gI][i];
            }
        }
    }
    #pragma unroll
    for (int o = 16; o; o >>= 1) s += __shfl_xor_sync(0xffffffffu, s, o);
    const float inv = 1.0f / s;

    #pragma unroll
    for (int gI = 0; gI < 4; gI++) {
        if (gI < ng) {
            uint2 o;
            o.x = pack_h(f[gI][0] * inv, f[gI][1] * inv);
            o.y = pack_h(f[gI][2] * inv, f[gI][3] * inv);
            p[gI * 32 + lane] = o;
        }
    }
}

// ---------------------------------------------------------------------------
// Launch (my index 3 = scores GEMM — the launch ncu profiles)
// ---------------------------------------------------------------------------
extern "C" void kernel_launch(void* const* d_in, const int* in_sizes, int n_in,
                              void* d_out, int out_size)
{
    const float* q   = (const float*)d_in[0];
    const float* k   = (const float*)d_in[1];
    const float* v   = (const float*)d_in[2];
    const float* pad = (const float*)d_in[3];
    // d_in[4] = attn_mask (causal applied analytically)
    const float* Wq  = (const float*)d_in[5];
    const float* Wk  = (const float*)d_in[6];
    const float* Wv  = (const float*)d_in[7];
    const float* Wo  = (const float*)d_in[8];
    const float* bo  = (const float*)d_in[9];
    float* out = (float*)d_out;

    fp16 *qh, *kh, *vh, *Wqh, *Wkh, *Wvh, *Woh;
    fp16 *Qh, *Kh, *Vth, *Ph, *Ch;
    cudaGetSymbolAddress((void**)&qh,  g_qh);
    cudaGetSymbolAddress((void**)&kh,  g_kh);
    cudaGetSymbolAddress((void**)&vh,  g_vh);
    cudaGetSymbolAddress((void**)&Wqh, g_Wqh);
    cudaGetSymbolAddress((void**)&Wkh, g_Wkh);
    cudaGetSymbolAddress((void**)&Wvh, g_Wvh);
    cudaGetSymbolAddress((void**)&Woh, g_Woh);
    cudaGetSymbolAddress((void**)&Qh,  g_Qh);
    cudaGetSymbolAddress((void**)&Kh,  g_Kh);
    cudaGetSymbolAddress((void**)&Vth, g_Vth);
    cudaGetSymbolAddress((void**)&Ph,  g_Ph);
    cudaGetSymbolAddress((void**)&Ch,  g_Ch);

    cudaFuncSetAttribute((const void*)gemm_hf<0>, cudaFuncAttributeMaxDynamicSharedMemorySize, SM_SMEM);
    cudaFuncSetAttribute((const void*)gemm_hf<2>, cudaFuncAttributeMaxDynamicSharedMemorySize, SM_SMEM);
    cudaFuncSetAttribute((const void*)gemm_hf<3>, cudaFuncAttributeMaxDynamicSharedMemorySize, SM_SMEM);
    cudaFuncSetAttribute((const void*)gemm_hf<4>, cudaFuncAttributeMaxDynamicSharedMemorySize, SM_SMEM);

    const int n4x = Mn * En / 4;          // 1048576
    const int n4w = Hn * En * En / 4;     // 131072 (== En*HEn/4 for Wo)

    // index 0-1: batched conversions
    cvt3_hi<<<dim3(n4x / 256, 3), 256>>>(q, k, v, qh, kh, vh, n4x);
    cvt4_hi<<<dim3(n4w / 256, 4), 256>>>(Wq, Wk, Wv, Wo, Wqh, Wkh, Wvh, Woh, n4w);

    // index 2: merged QKV projections, grid (2,128,24)
    gemm_hf<0><<<dim3(2, 128, 24), 256, SM_SMEM>>>(
        qh, kh, vh, Wqh, Wkh, Wvh, Qh, Kh, Vth, pad, nullptr);

    // index 3 (profiled): scores -> fp16 into P buffer, 10 tiles x 256 bh
    gemm_hf<2><<<dim3(10, 1, 256), 256, SM_SMEM>>>(
        Qh, nullptr, nullptr, Kh, nullptr, nullptr, Ph, nullptr, nullptr,
        nullptr, nullptr);

    // in-place warp-per-row softmax: 131072 rows / 16 per block
    softmax_inplace<<<BHn * Sn / 16, 512>>>(Ph);

    // attn @ V: (2,4,256), K truncated at causal boundary
    gemm_hf<3><<<dim3(2, 4, 256), 256, SM_SMEM>>>(
        Ph, nullptr, nullptr, Vth, nullptr, nullptr, Ch, nullptr, nullptr,
        nullptr, nullptr);

    // out projection: (2,128)
    gemm_hf<4><<<dim3(2, 128, 1), 256, SM_SMEM>>>(
        Ch, nullptr, nullptr, Woh, nullptr, nullptr, out, nullptr, nullptr,
        nullptr, bo);
}